// round 14
// baseline (speedup 1.0000x reference)
#include <cuda_runtime.h>
#include <cuda_fp16.h>
#include <cstdint>

#define RGR   4
#define NNODE 4033
#define RN    (RGR*NNODE)      // 16132
#define XROWS 16256
#define FINF  256
#define NH    8
#define NGRAPH 16
#define WKEPT 132
#define OUTN4 16265089          // 4033 * 4033 float4-chunks
#define XPAIRS (RN*128)
#define WPAIRS (2*512*128)
#define CONVN  (XPAIRS + WPAIRS)

__constant__ int c_len[NGRAPH] = {251, 247, 263, 255, 240, 258, 249, 260,
                                  252, 245, 256, 250, 248, 261, 244, 254};

__device__ __half g_Xh[(size_t)XROWS * FINF];
__device__ __half g_Wh[2 * 512 * FINF];
__device__ uint32_t g_Qf[(size_t)RN * 256];
__device__ uint32_t g_Kf[(size_t)RN * 256];
__device__ int      g_qnode[WKEPT * 32];
__device__ int      g_knode[WKEPT * 96];
__device__ int      g_lo[NNODE];
__device__ int      g_hi[NNODE];

// ---------------- band-aware zero-fill (runs concurrent with attn) ----------------
__global__ __launch_bounds__(256) void k_fill(float4* __restrict__ o) {
    uint32_t i = blockIdx.x * 256 + threadIdx.x;
    if (i >= OUTN4) return;
    uint32_t row = i / 4033u;
    uint32_t c4  = i - row * 4033u;
    const int lo = g_lo[row], hi = g_hi[row];
    const int col0 = (int)c4 * 4;
    unsigned outm = 0;   // bit e set => col0+e is OUTSIDE band (needs zero)
#pragma unroll
    for (int e = 0; e < 4; ++e) {
        int col = col0 + e;
        int r = (col >= 3 * NNODE) ? 3 : (col >= 2 * NNODE) ? 2 : (col >= NNODE) ? 1 : 0;
        int cc = col - r * NNODE;
        if (cc < lo || cc > hi) outm |= 1u << e;
    }
    if (outm == 15u) {
        o[i] = make_float4(0.f, 0.f, 0.f, 0.f);
    } else if (outm) {
        float* p = (float*)&o[i];
#pragma unroll
        for (int e = 0; e < 4; ++e)
            if ((outm >> e) & 1) p[e] = 0.f;
    }
}

// ---------------- convert X/W to fp16 + build index tables ----------------
__global__ __launch_bounds__(256) void k_conv(const float* __restrict__ X,
                                              const float* __restrict__ Wq,
                                              const float* __restrict__ Wk) {
    if (blockIdx.x == 0) {
        __shared__ int len[NGRAPH], start[NGRAPH], cum[NGRAPH], keptst[NGRAPH];
        if (threadIdx.x == 0) {
            int s = 0, c = 0, k = 0;
            for (int g = 0; g < NGRAPH; ++g) {
                int l = c_len[g];
                int t = ((l + 31) / 32) * 32 + 32;
                len[g] = l; start[g] = s; cum[g] = c; keptst[g] = k;
                s += t; c += l; k += t / 32 - 1;
            }
        }
        __syncthreads();
        for (int t = threadIdx.x; t < WKEPT * 128; t += blockDim.x) {
            int wk = t >> 7, slot = t & 127;
            int g = 0;
            while (g < NGRAPH - 1 && keptst[g + 1] <= wk) ++g;
            int wi = start[g] / 32 + (wk - keptst[g]);
            int p  = (slot < 32) ? (wi * 32 + slot) : (wi * 32 - 32 + (slot - 32));
            int node = -1;
            if (p >= 0) {
                int gg = 0;
                while (gg < NGRAPH - 1 && start[gg + 1] <= p) ++gg;
                int off = p - start[gg];
                if (off < len[gg]) node = cum[gg] + off;
            }
            if (slot < 32) g_qnode[wk * 32 + slot] = node;
            else           g_knode[wk * 96 + (slot - 32)] = node;
        }
        // per-node band range [lo, hi]
        for (int n = threadIdx.x; n < NNODE; n += blockDim.x) {
            int g = 0;
            while (g < NGRAPH - 1 && cum[g + 1] <= n) ++g;
            int off = n - cum[g];
            int p = start[g] + off;
            int wi = p >> 5;
            int lo_off = (wi - 1) * 32 - start[g];
            if (lo_off < 0) lo_off = 0;
            int hi_off = wi * 32 + 63 - start[g];
            if (hi_off > len[g] - 1) hi_off = len[g] - 1;
            g_lo[n] = cum[g] + lo_off;
            g_hi[n] = cum[g] + hi_off;
        }
        return;
    }
    int idx = (blockIdx.x - 1) * 256 + threadIdx.x;
    if (idx >= CONVN) return;
    if (idx < XPAIRS) {
        float2 v = *(const float2*)(X + (size_t)idx * 2);
        *(__half2*)&g_Xh[(size_t)idx * 2] = __floats2half2_rn(v.x, v.y);
    } else {
        int j = idx - XPAIRS;
        int sel = j >> 16, p = j & 65535;
        const float* W = sel ? Wk : Wq;
        float2 v = *(const float2*)(W + (size_t)p * 2);
        *(__half2*)&g_Wh[sel * (512 * FINF) + (size_t)p * 2] = __floats2half2_rn(v.x, v.y);
    }
}

// ---------------- helpers ----------------
__device__ __forceinline__ uint32_t smem_u32(const void* p) {
    uint32_t a;
    asm("{ .reg .u64 t; cvta.to.shared.u64 t, %1; cvt.u32.u64 %0, t; }" : "=r"(a) : "l"(p));
    return a;
}
__device__ __forceinline__ void cpa16(uint32_t dst, const void* src) {
    asm volatile("cp.async.cg.shared.global [%0], [%1], 16;" :: "r"(dst), "l"(src));
}
__device__ __forceinline__ void cpa_commit() {
    asm volatile("cp.async.commit_group;" ::: "memory");
}
template<int N> __device__ __forceinline__ void cpa_wait() {
    asm volatile("cp.async.wait_group %0;" :: "n"(N) : "memory");
}
__device__ __forceinline__ void ldsm4(uint32_t& x, uint32_t& y, uint32_t& z, uint32_t& w,
                                      uint32_t addr) {
    asm volatile("ldmatrix.sync.aligned.m8n8.x4.shared.b16 {%0,%1,%2,%3}, [%4];"
                 : "=r"(x), "=r"(y), "=r"(z), "=r"(w) : "r"(addr));
}
__device__ __forceinline__ void mma_f16(float& c0, float& c1, float& c2, float& c3,
                                        uint32_t a0, uint32_t a1, uint32_t a2, uint32_t a3,
                                        uint32_t b0, uint32_t b1) {
    asm volatile(
        "mma.sync.aligned.m16n8k16.row.col.f32.f16.f16.f32 "
        "{%0,%1,%2,%3}, {%4,%5,%6,%7}, {%8,%9}, {%0,%1,%2,%3};"
        : "+f"(c0), "+f"(c1), "+f"(c2), "+f"(c3)
        : "r"(a0), "r"(a1), "r"(a2), "r"(a3), "r"(b0), "r"(b1));
}

// ---------------- fp16 HMMA GEMM: 4-stage cp.async + ldmatrix ----------------
#define KC     32
#define NCH    (FINF / KC)
#define NSTG   4
#define ROWB   80
#define MATB   (128 * ROWB)
#define STGB   (2 * MATB)

__global__ __launch_bounds__(256, 2) void k_gemm_mma(const float* __restrict__ bq,
                                                     const float* __restrict__ bk) {
    extern __shared__ __align__(16) char smc[];
    const uint32_t sbase = smem_u32(smc);

    const int tid  = threadIdx.x;
    const int m0   = blockIdx.x * 128;
    const int sel  = blockIdx.y >> 2;
    const int cslc = (blockIdx.y & 3) * 128;
    const float* bias = sel ? bk : bq;
    const __half* Wh  = g_Wh + sel * (512 * FINF);
    uint32_t* Outf    = sel ? g_Kf : g_Qf;

    const int w    = tid >> 5, lane = tid & 31;
    const int wm   = w >> 1, wn = w & 1;
    const int lr   = lane >> 2;
    const int qp   = (lane & 3) * 2;

    const int row0 = tid >> 2, pc0 = tid & 3;
    const int row1 = (tid + 256) >> 2, pc1 = tid & 3;
    const uint32_t a_off = (uint32_t)((lane & 15) * ROWB + (lane >> 4) * 16);
    const uint32_t b_off = (uint32_t)((((lane >> 4) & 1) * 8 + (lane & 7)) * ROWB
                                      + ((lane >> 3) & 1) * 16);

    float c[2][8][4] = {};

#pragma unroll
    for (int st = 0; st < NSTG - 1; ++st) {
        const uint32_t sb = sbase + st * STGB;
        cpa16(sb + row0 * ROWB + pc0 * 16, g_Xh + (size_t)(m0 + row0) * FINF + st * KC + pc0 * 8);
        cpa16(sb + row1 * ROWB + pc1 * 16, g_Xh + (size_t)(m0 + row1) * FINF + st * KC + pc1 * 8);
        cpa16(sb + MATB + row0 * ROWB + pc0 * 16, Wh + (size_t)(cslc + row0) * FINF + st * KC + pc0 * 8);
        cpa16(sb + MATB + row1 * ROWB + pc1 * 16, Wh + (size_t)(cslc + row1) * FINF + st * KC + pc1 * 8);
        cpa_commit();
    }

    for (int kc = 0; kc < NCH; ++kc) {
        cpa_wait<NSTG - 2>();
        __syncthreads();

        const int kn = kc + NSTG - 1;
        if (kn < NCH) {
            const uint32_t sb = sbase + (kn & (NSTG - 1)) * STGB;
            cpa16(sb + row0 * ROWB + pc0 * 16, g_Xh + (size_t)(m0 + row0) * FINF + kn * KC + pc0 * 8);
            cpa16(sb + row1 * ROWB + pc1 * 16, g_Xh + (size_t)(m0 + row1) * FINF + kn * KC + pc1 * 8);
            cpa16(sb + MATB + row0 * ROWB + pc0 * 16, Wh + (size_t)(cslc + row0) * FINF + kn * KC + pc0 * 8);
            cpa16(sb + MATB + row1 * ROWB + pc1 * 16, Wh + (size_t)(cslc + row1) * FINF + kn * KC + pc1 * 8);
        }
        cpa_commit();

        const uint32_t Ab = sbase + (kc & (NSTG - 1)) * STGB;
        const uint32_t Bb = Ab + MATB;
#pragma unroll
        for (int ks = 0; ks < 2; ++ks) {
            uint32_t a0[4], a1[4];
            ldsm4(a0[0], a0[1], a0[2], a0[3],
                  Ab + (uint32_t)((wm * 32) * ROWB + ks * 32) + a_off);
            ldsm4(a1[0], a1[1], a1[2], a1[3],
                  Ab + (uint32_t)((wm * 32 + 16) * ROWB + ks * 32) + a_off);
#pragma unroll
            for (int np = 0; np < 4; ++np) {
                uint32_t b0, b1, b2, b3;
                ldsm4(b0, b1, b2, b3,
                      Bb + (uint32_t)((wn * 64 + np * 16) * ROWB + ks * 32) + b_off);
                mma_f16(c[0][2*np][0], c[0][2*np][1], c[0][2*np][2], c[0][2*np][3],
                        a0[0], a0[1], a0[2], a0[3], b0, b1);
                mma_f16(c[1][2*np][0], c[1][2*np][1], c[1][2*np][2], c[1][2*np][3],
                        a1[0], a1[1], a1[2], a1[3], b0, b1);
                mma_f16(c[0][2*np+1][0], c[0][2*np+1][1], c[0][2*np+1][2], c[0][2*np+1][3],
                        a0[0], a0[1], a0[2], a0[3], b2, b3);
                mma_f16(c[1][2*np+1][0], c[1][2*np+1][1], c[1][2*np+1][2], c[1][2*np+1][3],
                        a1[0], a1[1], a1[2], a1[3], b2, b3);
            }
        }
    }

#pragma unroll
    for (int mt = 0; mt < 2; ++mt) {
#pragma unroll
        for (int half = 0; half < 2; ++half) {
            int m = m0 + wm * 32 + mt * 16 + lr + half * 8;
            if (m >= RN) continue;
            int rel = m / NNODE, node = m - rel * NNODE;
#pragma unroll
            for (int nt = 0; nt < 8; ++nt) {
                int col = cslc + wn * 64 + nt * 8 + qp;
                int h = col >> 6;
                int d = nt * 8 + qp;
                int j = d >> 1;
                int u = j & 7, ks = j >> 3;
                int slot = ks * 8 + ((u < 4) ? 2 * u : 2 * (u - 4) + 1);
                float v0 = c[mt][nt][half * 2 + 0] + bias[col];
                float v1 = c[mt][nt][half * 2 + 1] + bias[col + 1];
                __half2 hv = __floats2half2_rn(v0, v1);
                Outf[((size_t)(rel * NH + h) * NNODE + node) * 32 + slot] = *(uint32_t*)&hv;
            }
        }
    }
}

// ---------------- fused attention ----------------
__global__ __launch_bounds__(256, 3) void k_attn(float* __restrict__ out) {
    const int wk = blockIdx.x, rel = blockIdx.y, mz = blockIdx.z;
    __shared__ int qn[16], kn[96];
    __shared__ __half sp[NH][16 * 96];
    __shared__ float  fac[NH][16][2];
    const int tid = threadIdx.x;
    if (tid < 16) qn[tid] = g_qnode[wk * 32 + mz * 16 + tid];
    if (tid < 96) kn[tid] = g_knode[wk * 96 + tid];
    __syncthreads();

    const int h = tid >> 5, lane = tid & 31;
    const int q = lane & 3, lr = lane >> 2;
    const size_t plane = (size_t)(rel * NH + h) * NNODE * 32;
    const uint32_t* Af = g_Qf + plane;
    const uint32_t* Bf = g_Kf + plane;

    const int qn0 = qn[lr], qn1 = qn[lr + 8];
    const float NEG = -3.402823466e38f;
    const uint2 Z2 = make_uint2(0u, 0u);

    float mrow[2][2], srow[2][2];

#pragma unroll
    for (int kh = 0; kh < 2; ++kh) {
        const int cb = kh * 48;
        int nb[6];
        unsigned vm0 = 0, vm1 = 0;
#pragma unroll
        for (int nt = 0; nt < 6; ++nt) {
            nb[nt] = kn[cb + nt * 8 + lr];
            if (kn[cb + nt * 8 + 2 * q] >= 0)     vm0 |= 1u << nt;
            if (kn[cb + nt * 8 + 2 * q + 1] >= 0) vm1 |= 1u << nt;
        }
        float c[6][4] = {};
#pragma unroll
        for (int ks = 0; ks < 4; ++ks) {
            const int so = ks * 8 + 2 * q;
            uint2 A0 = (qn0 >= 0) ? *(const uint2*)(Af + (size_t)qn0 * 32 + so) : Z2;
            uint2 A1 = (qn1 >= 0) ? *(const uint2*)(Af + (size_t)qn1 * 32 + so) : Z2;
#pragma unroll
            for (int nt = 0; nt < 6; ++nt) {
                int nd = nb[nt];
                uint2 B = (nd >= 0) ? *(const uint2*)(Bf + (size_t)nd * 32 + so) : Z2;
                mma_f16(c[nt][0], c[nt][1], c[nt][2], c[nt][3],
                        A0.x, A1.x, A0.y, A1.y, B.x, B.y);
            }
        }
#pragma unroll
        for (int nt = 0; nt < 6; ++nt) {
            bool v0 = (vm0 >> nt) & 1, v1 = (vm1 >> nt) & 1;
            c[nt][0] = v0 ? c[nt][0] * 0.125f : NEG;
            c[nt][1] = v1 ? c[nt][1] * 0.125f : NEG;
            c[nt][2] = v0 ? c[nt][2] * 0.125f : NEG;
            c[nt][3] = v1 ? c[nt][3] * 0.125f : NEG;
        }
        float m0 = NEG, m1 = NEG;
#pragma unroll
        for (int nt = 0; nt < 6; ++nt) {
            m0 = fmaxf(m0, fmaxf(c[nt][0], c[nt][1]));
            m1 = fmaxf(m1, fmaxf(c[nt][2], c[nt][3]));
        }
        m0 = fmaxf(m0, __shfl_xor_sync(0xffffffffu, m0, 1, 4));
        m0 = fmaxf(m0, __shfl_xor_sync(0xffffffffu, m0, 2, 4));
        m1 = fmaxf(m1, __shfl_xor_sync(0xffffffffu, m1, 1, 4));
        m1 = fmaxf(m1, __shfl_xor_sync(0xffffffffu, m1, 2, 4));
        float s0 = 0.f, s1 = 0.f;
#pragma unroll
        for (int nt = 0; nt < 6; ++nt) {
            c[nt][0] = __expf(c[nt][0] - m0); s0 += c[nt][0];
            c[nt][1] = __expf(c[nt][1] - m0); s0 += c[nt][1];
            c[nt][2] = __expf(c[nt][2] - m1); s1 += c[nt][2];
            c[nt][3] = __expf(c[nt][3] - m1); s1 += c[nt][3];
        }
        s0 += __shfl_xor_sync(0xffffffffu, s0, 1, 4);
        s0 += __shfl_xor_sync(0xffffffffu, s0, 2, 4);
        s1 += __shfl_xor_sync(0xffffffffu, s1, 1, 4);
        s1 += __shfl_xor_sync(0xffffffffu, s1, 2, 4);
        mrow[0][kh] = m0; srow[0][kh] = s0;
        mrow[1][kh] = m1; srow[1][kh] = s1;

        __half* r0p = &sp[h][lr * 96 + cb + 2 * q];
        __half* r1p = r0p + 8 * 96;
#pragma unroll
        for (int nt = 0; nt < 6; ++nt) {
            *(__half2*)(r0p + nt * 8) = __floats2half2_rn(c[nt][0], c[nt][1]);
            *(__half2*)(r1p + nt * 8) = __floats2half2_rn(c[nt][2], c[nt][3]);
        }
    }

    if (q == 0) {
#pragma unroll
        for (int r = 0; r < 2; ++r) {
            float Ma = fmaxf(mrow[r][0], mrow[r][1]);
            float e0 = __expf(mrow[r][0] - Ma), e1 = __expf(mrow[r][1] - Ma);
            float tot = srow[r][0] * e0 + srow[r][1] * e1;
            float inv = 0.125f / tot;
            fac[h][lr + r * 8][0] = e0 * inv;
            fac[h][lr + r * 8][1] = e1 * inv;
        }
    }
    __syncthreads();

    // head-sum + scatter: half2 per thread-iteration (2 adjacent cols)
    for (int idx2 = tid; idx2 < 16 * 48; idx2 += 256) {
        int row = idx2 / 48, cp = (idx2 - row * 48) * 2;
        int nq = qn[row];
        if (nq < 0) continue;
        int nk0 = kn[cp], nk1 = kn[cp + 1];
        if ((nk0 | nk1) < 0 && nk0 < 0 && nk1 < 0) continue;
        int kh = cp >= 48;
        float s0 = 0.f, s1 = 0.f;
#pragma unroll
        for (int hh = 0; hh < NH; ++hh) {
            float2 v = __half22float2(*(const __half2*)&sp[hh][row * 96 + cp]);
            float f = fac[hh][row][kh];
            s0 += v.x * f; s1 += v.y * f;
        }
        float* orow = out + (size_t)nq * RN + (size_t)rel * NNODE;
        if (nk0 >= 0) orow[nk0] = s0;
        if (nk1 >= 0) orow[nk1] = s1;
    }
}

// ---------------- launch ----------------
static cudaStream_t s_side = nullptr;
static cudaEvent_t  ev_fork = nullptr, ev_join = nullptr;

extern "C" void kernel_launch(void* const* d_in, const int* in_sizes, int n_in,
                              void* d_out, int out_size) {
    const float* X  = (const float*)d_in[0];
    const float* Wq = (const float*)d_in[1];
    const float* bq = (const float*)d_in[2];
    const float* Wk = (const float*)d_in[3];
    const float* bk = (const float*)d_in[4];
    float* out = (float*)d_out;

    const int smem_bytes = NSTG * STGB;      // 80 KB
    if (!s_side) {
        cudaStreamCreateWithFlags(&s_side, cudaStreamNonBlocking);
        cudaEventCreateWithFlags(&ev_fork, cudaEventDisableTiming);
        cudaEventCreateWithFlags(&ev_join, cudaEventDisableTiming);
        cudaFuncSetAttribute(k_gemm_mma, cudaFuncAttributeMaxDynamicSharedMemorySize,
                             smem_bytes);
    }

    // conv (also builds index + band tables)
    k_conv<<<(CONVN + 255) / 256 + 1, 256>>>(X, Wq, Wk);

    // fork: band-complement fill runs concurrent with GEMM + attention
    cudaEventRecord(ev_fork, 0);
    cudaStreamWaitEvent(s_side, ev_fork, 0);
    k_fill<<<(OUTN4 + 255) / 256, 256, 0, s_side>>>((float4*)out);
    cudaEventRecord(ev_join, s_side);

    k_gemm_mma<<<dim3(127, 8), 256, smem_bytes>>>(bq, bk);
    k_attn<<<dim3(WKEPT, RGR, 2), 256>>>(out);

    // join: fill must complete before harness reads
    cudaStreamWaitEvent(0, ev_join, 0);
}

// round 15
// speedup vs baseline: 1.1503x; 1.1503x over previous
#include <cuda_runtime.h>
#include <cuda_fp16.h>
#include <cstdint>

#define RGR   4
#define NNODE 4033
#define RN    (RGR*NNODE)      // 16132
#define XROWS 16256
#define FINF  256
#define NH    8
#define NGRAPH 16
#define WKEPT 132
#define OUTN4 16265089          // 4033 * 4033 float4-chunks
#define XPAIRS (RN*128)
#define WPAIRS (2*512*128)
#define CONVN  (XPAIRS + WPAIRS)

__constant__ int c_len[NGRAPH] = {251, 247, 263, 255, 240, 258, 249, 260,
                                  252, 245, 256, 250, 248, 261, 244, 254};

__device__ __half g_Xh[(size_t)XROWS * FINF];
__device__ __half g_Wh[2 * 512 * FINF];
__device__ uint32_t g_Qf[(size_t)RN * 256];
__device__ uint32_t g_Kf[(size_t)RN * 256];
__device__ int      g_qnode[WKEPT * 32];
__device__ int      g_knode[WKEPT * 96];

// ---------------- grid-stride zero-fill (high per-thread MLP) ----------------
#define FILLBLK 2368
__global__ __launch_bounds__(256) void k_zero(float4* __restrict__ o) {
    const float4 z = make_float4(0.f, 0.f, 0.f, 0.f);
    const uint32_t stride = FILLBLK * 256;
    for (uint32_t i = blockIdx.x * 256 + threadIdx.x; i < OUTN4; i += stride)
        o[i] = z;
}

// ---------------- convert X/W to fp16 + build index tables ----------------
__global__ __launch_bounds__(256) void k_conv(const float* __restrict__ X,
                                              const float* __restrict__ Wq,
                                              const float* __restrict__ Wk) {
    if (blockIdx.x == 0) {
        __shared__ int len[NGRAPH], start[NGRAPH], cum[NGRAPH], keptst[NGRAPH];
        if (threadIdx.x == 0) {
            int s = 0, c = 0, k = 0;
            for (int g = 0; g < NGRAPH; ++g) {
                int l = c_len[g];
                int t = ((l + 31) / 32) * 32 + 32;
                len[g] = l; start[g] = s; cum[g] = c; keptst[g] = k;
                s += t; c += l; k += t / 32 - 1;
            }
        }
        __syncthreads();
        for (int t = threadIdx.x; t < WKEPT * 128; t += blockDim.x) {
            int wk = t >> 7, slot = t & 127;
            int g = 0;
            while (g < NGRAPH - 1 && keptst[g + 1] <= wk) ++g;
            int wi = start[g] / 32 + (wk - keptst[g]);
            int p  = (slot < 32) ? (wi * 32 + slot) : (wi * 32 - 32 + (slot - 32));
            int node = -1;
            if (p >= 0) {
                int gg = 0;
                while (gg < NGRAPH - 1 && start[gg + 1] <= p) ++gg;
                int off = p - start[gg];
                if (off < len[gg]) node = cum[gg] + off;
            }
            if (slot < 32) g_qnode[wk * 32 + slot] = node;
            else           g_knode[wk * 96 + (slot - 32)] = node;
        }
        return;
    }
    int idx = (blockIdx.x - 1) * 256 + threadIdx.x;
    if (idx >= CONVN) return;
    if (idx < XPAIRS) {
        float2 v = *(const float2*)(X + (size_t)idx * 2);
        *(__half2*)&g_Xh[(size_t)idx * 2] = __floats2half2_rn(v.x, v.y);
    } else {
        int j = idx - XPAIRS;
        int sel = j >> 16, p = j & 65535;
        const float* W = sel ? Wk : Wq;
        float2 v = *(const float2*)(W + (size_t)p * 2);
        *(__half2*)&g_Wh[sel * (512 * FINF) + (size_t)p * 2] = __floats2half2_rn(v.x, v.y);
    }
}

// ---------------- helpers ----------------
__device__ __forceinline__ uint32_t smem_u32(const void* p) {
    uint32_t a;
    asm("{ .reg .u64 t; cvta.to.shared.u64 t, %1; cvt.u32.u64 %0, t; }" : "=r"(a) : "l"(p));
    return a;
}
__device__ __forceinline__ void cpa16(uint32_t dst, const void* src) {
    asm volatile("cp.async.cg.shared.global [%0], [%1], 16;" :: "r"(dst), "l"(src));
}
__device__ __forceinline__ void cpa_commit() {
    asm volatile("cp.async.commit_group;" ::: "memory");
}
template<int N> __device__ __forceinline__ void cpa_wait() {
    asm volatile("cp.async.wait_group %0;" :: "n"(N) : "memory");
}
__device__ __forceinline__ void ldsm4(uint32_t& x, uint32_t& y, uint32_t& z, uint32_t& w,
                                      uint32_t addr) {
    asm volatile("ldmatrix.sync.aligned.m8n8.x4.shared.b16 {%0,%1,%2,%3}, [%4];"
                 : "=r"(x), "=r"(y), "=r"(z), "=r"(w) : "r"(addr));
}
__device__ __forceinline__ void mma_f16(float& c0, float& c1, float& c2, float& c3,
                                        uint32_t a0, uint32_t a1, uint32_t a2, uint32_t a3,
                                        uint32_t b0, uint32_t b1) {
    asm volatile(
        "mma.sync.aligned.m16n8k16.row.col.f32.f16.f16.f32 "
        "{%0,%1,%2,%3}, {%4,%5,%6,%7}, {%8,%9}, {%0,%1,%2,%3};"
        : "+f"(c0), "+f"(c1), "+f"(c2), "+f"(c3)
        : "r"(a0), "r"(a1), "r"(a2), "r"(a3), "r"(b0), "r"(b1));
}

// ---------------- fp16 HMMA GEMM: 4-stage cp.async + ldmatrix ----------------
#define KC     32
#define NCH    (FINF / KC)
#define NSTG   4
#define ROWB   80
#define MATB   (128 * ROWB)
#define STGB   (2 * MATB)

__global__ __launch_bounds__(256, 2) void k_gemm_mma(const float* __restrict__ bq,
                                                     const float* __restrict__ bk) {
    extern __shared__ __align__(16) char smc[];
    const uint32_t sbase = smem_u32(smc);

    const int tid  = threadIdx.x;
    const int m0   = blockIdx.x * 128;
    const int sel  = blockIdx.y >> 2;
    const int cslc = (blockIdx.y & 3) * 128;
    const float* bias = sel ? bk : bq;
    const __half* Wh  = g_Wh + sel * (512 * FINF);
    uint32_t* Outf    = sel ? g_Kf : g_Qf;

    const int w    = tid >> 5, lane = tid & 31;
    const int wm   = w >> 1, wn = w & 1;
    const int lr   = lane >> 2;
    const int qp   = (lane & 3) * 2;

    const int row0 = tid >> 2, pc0 = tid & 3;
    const int row1 = (tid + 256) >> 2, pc1 = tid & 3;
    const uint32_t a_off = (uint32_t)((lane & 15) * ROWB + (lane >> 4) * 16);
    const uint32_t b_off = (uint32_t)((((lane >> 4) & 1) * 8 + (lane & 7)) * ROWB
                                      + ((lane >> 3) & 1) * 16);

    float c[2][8][4] = {};

#pragma unroll
    for (int st = 0; st < NSTG - 1; ++st) {
        const uint32_t sb = sbase + st * STGB;
        cpa16(sb + row0 * ROWB + pc0 * 16, g_Xh + (size_t)(m0 + row0) * FINF + st * KC + pc0 * 8);
        cpa16(sb + row1 * ROWB + pc1 * 16, g_Xh + (size_t)(m0 + row1) * FINF + st * KC + pc1 * 8);
        cpa16(sb + MATB + row0 * ROWB + pc0 * 16, Wh + (size_t)(cslc + row0) * FINF + st * KC + pc0 * 8);
        cpa16(sb + MATB + row1 * ROWB + pc1 * 16, Wh + (size_t)(cslc + row1) * FINF + st * KC + pc1 * 8);
        cpa_commit();
    }

    for (int kc = 0; kc < NCH; ++kc) {
        cpa_wait<NSTG - 2>();
        __syncthreads();

        const int kn = kc + NSTG - 1;
        if (kn < NCH) {
            const uint32_t sb = sbase + (kn & (NSTG - 1)) * STGB;
            cpa16(sb + row0 * ROWB + pc0 * 16, g_Xh + (size_t)(m0 + row0) * FINF + kn * KC + pc0 * 8);
            cpa16(sb + row1 * ROWB + pc1 * 16, g_Xh + (size_t)(m0 + row1) * FINF + kn * KC + pc1 * 8);
            cpa16(sb + MATB + row0 * ROWB + pc0 * 16, Wh + (size_t)(cslc + row0) * FINF + kn * KC + pc0 * 8);
            cpa16(sb + MATB + row1 * ROWB + pc1 * 16, Wh + (size_t)(cslc + row1) * FINF + kn * KC + pc1 * 8);
        }
        cpa_commit();

        const uint32_t Ab = sbase + (kc & (NSTG - 1)) * STGB;
        const uint32_t Bb = Ab + MATB;
#pragma unroll
        for (int ks = 0; ks < 2; ++ks) {
            uint32_t a0[4], a1[4];
            ldsm4(a0[0], a0[1], a0[2], a0[3],
                  Ab + (uint32_t)((wm * 32) * ROWB + ks * 32) + a_off);
            ldsm4(a1[0], a1[1], a1[2], a1[3],
                  Ab + (uint32_t)((wm * 32 + 16) * ROWB + ks * 32) + a_off);
#pragma unroll
            for (int np = 0; np < 4; ++np) {
                uint32_t b0, b1, b2, b3;
                ldsm4(b0, b1, b2, b3,
                      Bb + (uint32_t)((wn * 64 + np * 16) * ROWB + ks * 32) + b_off);
                mma_f16(c[0][2*np][0], c[0][2*np][1], c[0][2*np][2], c[0][2*np][3],
                        a0[0], a0[1], a0[2], a0[3], b0, b1);
                mma_f16(c[1][2*np][0], c[1][2*np][1], c[1][2*np][2], c[1][2*np][3],
                        a1[0], a1[1], a1[2], a1[3], b0, b1);
                mma_f16(c[0][2*np+1][0], c[0][2*np+1][1], c[0][2*np+1][2], c[0][2*np+1][3],
                        a0[0], a0[1], a0[2], a0[3], b2, b3);
                mma_f16(c[1][2*np+1][0], c[1][2*np+1][1], c[1][2*np+1][2], c[1][2*np+1][3],
                        a1[0], a1[1], a1[2], a1[3], b2, b3);
            }
        }
    }

#pragma unroll
    for (int mt = 0; mt < 2; ++mt) {
#pragma unroll
        for (int half = 0; half < 2; ++half) {
            int m = m0 + wm * 32 + mt * 16 + lr + half * 8;
            if (m >= RN) continue;
            int rel = m / NNODE, node = m - rel * NNODE;
#pragma unroll
            for (int nt = 0; nt < 8; ++nt) {
                int col = cslc + wn * 64 + nt * 8 + qp;
                int h = col >> 6;
                int d = nt * 8 + qp;
                int j = d >> 1;
                int u = j & 7, ks = j >> 3;
                int slot = ks * 8 + ((u < 4) ? 2 * u : 2 * (u - 4) + 1);
                float v0 = c[mt][nt][half * 2 + 0] + bias[col];
                float v1 = c[mt][nt][half * 2 + 1] + bias[col + 1];
                __half2 hv = __floats2half2_rn(v0, v1);
                Outf[((size_t)(rel * NH + h) * NNODE + node) * 32 + slot] = *(uint32_t*)&hv;
            }
        }
    }
}

// ---------------- fused attention ----------------
__global__ __launch_bounds__(256, 3) void k_attn(float* __restrict__ out) {
    const int wk = blockIdx.x, rel = blockIdx.y, mz = blockIdx.z;
    __shared__ int qn[16], kn[96];
    __shared__ __half sp[NH][16 * 96];
    __shared__ float  fac[NH][16][2];
    const int tid = threadIdx.x;
    if (tid < 16) qn[tid] = g_qnode[wk * 32 + mz * 16 + tid];
    if (tid < 96) kn[tid] = g_knode[wk * 96 + tid];
    __syncthreads();

    const int h = tid >> 5, lane = tid & 31;
    const int q = lane & 3, lr = lane >> 2;
    const size_t plane = (size_t)(rel * NH + h) * NNODE * 32;
    const uint32_t* Af = g_Qf + plane;
    const uint32_t* Bf = g_Kf + plane;

    const int qn0 = qn[lr], qn1 = qn[lr + 8];
    const float NEG = -3.402823466e38f;
    const uint2 Z2 = make_uint2(0u, 0u);

    float mrow[2][2], srow[2][2];

#pragma unroll
    for (int kh = 0; kh < 2; ++kh) {
        const int cb = kh * 48;
        int nb[6];
        unsigned vm0 = 0, vm1 = 0;
#pragma unroll
        for (int nt = 0; nt < 6; ++nt) {
            nb[nt] = kn[cb + nt * 8 + lr];
            if (kn[cb + nt * 8 + 2 * q] >= 0)     vm0 |= 1u << nt;
            if (kn[cb + nt * 8 + 2 * q + 1] >= 0) vm1 |= 1u << nt;
        }
        float c[6][4] = {};
#pragma unroll
        for (int ks = 0; ks < 4; ++ks) {
            const int so = ks * 8 + 2 * q;
            uint2 A0 = (qn0 >= 0) ? *(const uint2*)(Af + (size_t)qn0 * 32 + so) : Z2;
            uint2 A1 = (qn1 >= 0) ? *(const uint2*)(Af + (size_t)qn1 * 32 + so) : Z2;
#pragma unroll
            for (int nt = 0; nt < 6; ++nt) {
                int nd = nb[nt];
                uint2 B = (nd >= 0) ? *(const uint2*)(Bf + (size_t)nd * 32 + so) : Z2;
                mma_f16(c[nt][0], c[nt][1], c[nt][2], c[nt][3],
                        A0.x, A1.x, A0.y, A1.y, B.x, B.y);
            }
        }
#pragma unroll
        for (int nt = 0; nt < 6; ++nt) {
            bool v0 = (vm0 >> nt) & 1, v1 = (vm1 >> nt) & 1;
            c[nt][0] = v0 ? c[nt][0] * 0.125f : NEG;
            c[nt][1] = v1 ? c[nt][1] * 0.125f : NEG;
            c[nt][2] = v0 ? c[nt][2] * 0.125f : NEG;
            c[nt][3] = v1 ? c[nt][3] * 0.125f : NEG;
        }
        float m0 = NEG, m1 = NEG;
#pragma unroll
        for (int nt = 0; nt < 6; ++nt) {
            m0 = fmaxf(m0, fmaxf(c[nt][0], c[nt][1]));
            m1 = fmaxf(m1, fmaxf(c[nt][2], c[nt][3]));
        }
        m0 = fmaxf(m0, __shfl_xor_sync(0xffffffffu, m0, 1, 4));
        m0 = fmaxf(m0, __shfl_xor_sync(0xffffffffu, m0, 2, 4));
        m1 = fmaxf(m1, __shfl_xor_sync(0xffffffffu, m1, 1, 4));
        m1 = fmaxf(m1, __shfl_xor_sync(0xffffffffu, m1, 2, 4));
        float s0 = 0.f, s1 = 0.f;
#pragma unroll
        for (int nt = 0; nt < 6; ++nt) {
            c[nt][0] = __expf(c[nt][0] - m0); s0 += c[nt][0];
            c[nt][1] = __expf(c[nt][1] - m0); s0 += c[nt][1];
            c[nt][2] = __expf(c[nt][2] - m1); s1 += c[nt][2];
            c[nt][3] = __expf(c[nt][3] - m1); s1 += c[nt][3];
        }
        s0 += __shfl_xor_sync(0xffffffffu, s0, 1, 4);
        s0 += __shfl_xor_sync(0xffffffffu, s0, 2, 4);
        s1 += __shfl_xor_sync(0xffffffffu, s1, 1, 4);
        s1 += __shfl_xor_sync(0xffffffffu, s1, 2, 4);
        mrow[0][kh] = m0; srow[0][kh] = s0;
        mrow[1][kh] = m1; srow[1][kh] = s1;

        __half* r0p = &sp[h][lr * 96 + cb + 2 * q];
        __half* r1p = r0p + 8 * 96;
#pragma unroll
        for (int nt = 0; nt < 6; ++nt) {
            *(__half2*)(r0p + nt * 8) = __floats2half2_rn(c[nt][0], c[nt][1]);
            *(__half2*)(r1p + nt * 8) = __floats2half2_rn(c[nt][2], c[nt][3]);
        }
    }

    if (q == 0) {
#pragma unroll
        for (int r = 0; r < 2; ++r) {
            float Ma = fmaxf(mrow[r][0], mrow[r][1]);
            float e0 = __expf(mrow[r][0] - Ma), e1 = __expf(mrow[r][1] - Ma);
            float tot = srow[r][0] * e0 + srow[r][1] * e1;
            float inv = 0.125f / tot;
            fac[h][lr + r * 8][0] = e0 * inv;
            fac[h][lr + r * 8][1] = e1 * inv;
        }
    }
    __syncthreads();

    // head-sum + scatter: half2 per thread-iteration (2 adjacent cols)
    for (int idx2 = tid; idx2 < 16 * 48; idx2 += 256) {
        int row = idx2 / 48, cp = (idx2 - row * 48) * 2;
        int nq = qn[row];
        if (nq < 0) continue;
        int nk0 = kn[cp], nk1 = kn[cp + 1];
        if (nk0 < 0 && nk1 < 0) continue;
        int kh = cp >= 48;
        float s0 = 0.f, s1 = 0.f;
#pragma unroll
        for (int hh = 0; hh < NH; ++hh) {
            float2 v = __half22float2(*(const __half2*)&sp[hh][row * 96 + cp]);
            float f = fac[hh][row][kh];
            s0 += v.x * f; s1 += v.y * f;
        }
        float* orow = out + (size_t)nq * RN + (size_t)rel * NNODE;
        if (nk0 >= 0) orow[nk0] = s0;
        if (nk1 >= 0) orow[nk1] = s1;
    }
}

// ---------------- launch ----------------
static cudaStream_t s_side = nullptr;
static cudaEvent_t  ev_fork = nullptr, ev_join = nullptr;

extern "C" void kernel_launch(void* const* d_in, const int* in_sizes, int n_in,
                              void* d_out, int out_size) {
    const float* X  = (const float*)d_in[0];
    const float* Wq = (const float*)d_in[1];
    const float* bq = (const float*)d_in[2];
    const float* Wk = (const float*)d_in[3];
    const float* bk = (const float*)d_in[4];
    float* out = (float*)d_out;

    const int smem_bytes = NSTG * STGB;      // 80 KB
    if (!s_side) {
        cudaStreamCreateWithFlags(&s_side, cudaStreamNonBlocking);
        cudaEventCreateWithFlags(&ev_fork, cudaEventDisableTiming);
        cudaEventCreateWithFlags(&ev_join, cudaEventDisableTiming);
        cudaFuncSetAttribute(k_gemm_mma, cudaFuncAttributeMaxDynamicSharedMemorySize,
                             smem_bytes);
    }

    // fork: zero-fill runs concurrent with conv + GEMM
    cudaEventRecord(ev_fork, 0);
    cudaStreamWaitEvent(s_side, ev_fork, 0);
    k_zero<<<FILLBLK, 256, 0, s_side>>>((float4*)out);
    cudaEventRecord(ev_join, s_side);

    k_conv<<<(CONVN + 255) / 256 + 1, 256>>>(X, Wq, Wk);
    k_gemm_mma<<<dim3(127, 8), 256, smem_bytes>>>(bq, bk);

    // join: attn writes into the zeroed output
    cudaStreamWaitEvent(0, ev_join, 0);
    k_attn<<<dim3(WKEPT, RGR, 2), 256>>>(out);
}